// round 16
// baseline (speedup 1.0000x reference)
#include <cuda_runtime.h>
#include <mma.h>
#include <math.h>
#include <stdint.h>

using namespace nvcuda;

// Problem constants
constexpr int H_   = 16;
constexpr int D_   = 128;
constexpr int B_   = 2;
constexpr int S_   = 2048;
constexpr int DIM_ = 2048;
constexpr int EQKV = 3 * H_ * D_;   // 6144

// Scratch (device globals — allocation-free)
__device__ float g_qkv[(size_t)B_ * S_ * EQKV];        // [B,S,6144]
__device__ float g_attn[(size_t)B_ * S_ * H_ * D_];    // [B,S,2048]

// ---------------------------------------------------------------------------
// Helpers: tf32 convert + raw mma.m16n8k8 tf32 (verified fragment layouts, R13)
// ---------------------------------------------------------------------------
__device__ __forceinline__ float f2tf32(float x) {
    uint32_t u;
    asm("cvt.rna.tf32.f32 %0, %1;" : "=r"(u) : "f"(x));
    return __uint_as_float(u);
}

__device__ __forceinline__ void mma_tf32_16x8x8(
    float d[4], const float a[4], float b0, float b1)
{
    uint32_t a0 = __float_as_uint(a[0]), a1 = __float_as_uint(a[1]);
    uint32_t a2 = __float_as_uint(a[2]), a3 = __float_as_uint(a[3]);
    uint32_t bb0 = __float_as_uint(b0), bb1 = __float_as_uint(b1);
    asm volatile(
        "mma.sync.aligned.m16n8k8.row.col.f32.tf32.tf32.f32 "
        "{%0,%1,%2,%3}, {%4,%5,%6,%7}, {%8,%9}, {%0,%1,%2,%3};\n"
        : "+f"(d[0]), "+f"(d[1]), "+f"(d[2]), "+f"(d[3])
        : "r"(a0), "r"(a1), "r"(a2), "r"(a3), "r"(bb0), "r"(bb1));
}

// ---------------------------------------------------------------------------
// GEMM NT (tf32 wmma) — unchanged (passed R9/R13, tensor=42.5%).
// ---------------------------------------------------------------------------
constexpr int BM = 128, BN = 128, BK = 16;
constexpr int BK_PAD = BK + 4;

__global__ __launch_bounds__(256) void gemm_nt_tf32(
    const float* __restrict__ A, const float* __restrict__ Bmat,
    float* __restrict__ C, int M, int N, int K)
{
    __shared__ float As[2][BM][BK_PAD];
    __shared__ float Bs[2][BN][BK_PAD];

    const int tid = threadIdx.x;
    const int w   = tid >> 5;
    const int wr  = w & 3;
    const int wc  = w >> 2;
    const int rowBase = blockIdx.y * BM;
    const int colBase = blockIdx.x * BN;

    const int r0  = (tid + 0 * 256) >> 2;
    const int r1  = (tid + 1 * 256) >> 2;
    const int c4_ = (tid & 3) << 2;

    wmma::fragment<wmma::accumulator, 16, 16, 8, float> acc[2][4];
    #pragma unroll
    for (int i = 0; i < 2; i++)
        #pragma unroll
        for (int j = 0; j < 4; j++)
            wmma::fill_fragment(acc[i][j], 0.0f);

    auto stage = [&](int buf, int k0) {
        #pragma unroll
        for (int i = 0; i < 2; i++) {
            int r = (i == 0) ? r0 : r1;
            float4 va = *(const float4*)&A[(size_t)(rowBase + r) * K + k0 + c4_];
            As[buf][r][c4_ + 0] = wmma::__float_to_tf32(va.x);
            As[buf][r][c4_ + 1] = wmma::__float_to_tf32(va.y);
            As[buf][r][c4_ + 2] = wmma::__float_to_tf32(va.z);
            As[buf][r][c4_ + 3] = wmma::__float_to_tf32(va.w);
            float4 vb = *(const float4*)&Bmat[(size_t)(colBase + r) * K + k0 + c4_];
            Bs[buf][r][c4_ + 0] = wmma::__float_to_tf32(vb.x);
            Bs[buf][r][c4_ + 1] = wmma::__float_to_tf32(vb.y);
            Bs[buf][r][c4_ + 2] = wmma::__float_to_tf32(vb.z);
            Bs[buf][r][c4_ + 3] = wmma::__float_to_tf32(vb.w);
        }
    };

    stage(0, 0);
    __syncthreads();

    int cur = 0;
    for (int k0 = 0; k0 < K; k0 += BK) {
        if (k0 + BK < K) stage(cur ^ 1, k0 + BK);

        #pragma unroll
        for (int kk = 0; kk < BK; kk += 8) {
            wmma::fragment<wmma::matrix_a, 16, 16, 8, wmma::precision::tf32, wmma::row_major> af[2];
            wmma::fragment<wmma::matrix_b, 16, 16, 8, wmma::precision::tf32, wmma::col_major> bf[4];
            #pragma unroll
            for (int i = 0; i < 2; i++)
                wmma::load_matrix_sync(af[i], &As[cur][wr * 32 + i * 16][kk], BK_PAD);
            #pragma unroll
            for (int j = 0; j < 4; j++)
                wmma::load_matrix_sync(bf[j], &Bs[cur][wc * 64 + j * 16][kk], BK_PAD);
            #pragma unroll
            for (int i = 0; i < 2; i++)
                #pragma unroll
                for (int j = 0; j < 4; j++)
                    wmma::mma_sync(acc[i][j], af[i], bf[j], acc[i][j]);
        }
        __syncthreads();
        cur ^= 1;
    }

    #pragma unroll
    for (int i = 0; i < 2; i++)
        #pragma unroll
        for (int j = 0; j < 4; j++) {
            int r = rowBase + wr * 32 + i * 16;
            int c = colBase + wc * 64 + j * 16;
            wmma::store_matrix_sync(&C[(size_t)r * N + c], acc[i][j], N, wmma::mem_row_major);
        }
}

// ---------------------------------------------------------------------------
// Flash attention v3: spill-free. Q persistent in smem (reloaded per k-step),
// P layout conversion via quad shuffles (no Ss buffer), 2 barriers/KV tile.
// Live registers ~130 (o_[64] + sacc[32] + misc) — under the spill line.
// Fragment layouts (g=lane/4, t=lane%4), verified correct in R13:
//   A: a0(g,t) a1(g+8,t) a2(g,t+4) a3(g+8,t+4)
//   B: b0(n=g,k=t) b1(n=g,k=t+4)
//   C: c0(g,2t) c1(g,2t+1) c2(g+8,2t) c3(g+8,2t+1)
// ---------------------------------------------------------------------------
constexpr int BQ = 64, BKV = 64;
constexpr int QPAD = 132;   // (4g+t)%32 distinct for frag loads
constexpr int KPAD = 132;
constexpr int VPAD = 136;   // (8t+g)%32 distinct
constexpr size_t ATTN_SMEM =
    ((size_t)BQ * QPAD + (size_t)BKV * KPAD + (size_t)BKV * VPAD) * sizeof(float);

__global__ __launch_bounds__(128) void attn_kernel(
    const float* __restrict__ qkv, float* __restrict__ out)
{
    extern __shared__ float sm[];
    float* Qs = sm;                       // [64][QPAD], persistent
    float* Ks = Qs + BQ * QPAD;           // [64][KPAD]
    float* Vs = Ks + BKV * KPAD;          // [64][VPAD]

    const int tid  = threadIdx.x;
    const int lane = tid & 31;
    const int w    = tid >> 5;            // 0..3
    const int g    = lane >> 2;           // 0..7
    const int t    = lane & 3;            // 0..3
    const int qt = blockIdx.x, h = blockIdx.y, b = blockIdx.z;
    const float* base = qkv + (size_t)b * S_ * EQKV;
    const float scale = 0.08838834764831845f;   // 1/sqrt(128)

    // Shuffle source lanes for P layout conversion (C-frag -> A-frag):
    //   A col j=t   lives in C lane (g, t>>1),     reg parity t&1
    //   A col j=t+4 lives in C lane (g, 2 + (t>>1)), same parity
    const int src1 = (lane & 0x1C) | (t >> 1);
    const int src2 = src1 + 2;
    const bool odd = (t & 1);

    // ---- Stage Q tile (scaled, tf32) into persistent Qs ----
    #pragma unroll
    for (int i = 0; i < 16; i++) {
        int lin = tid + i * 128;              // float4 id, 0..2047
        int r   = lin >> 5;                   // 0..63
        int c4  = (lin & 31) << 2;            // 0..124
        float4 v = *(const float4*)&base[(size_t)(qt * BQ + r) * EQKV + h * D_ + c4];
        float4 o;
        o.x = f2tf32(v.x * scale); o.y = f2tf32(v.y * scale);
        o.z = f2tf32(v.z * scale); o.w = f2tf32(v.w * scale);
        *(float4*)&Qs[r * QPAD + c4] = o;
    }
    __syncthreads();

    float o_[16][4];                          // O: 16 n-frags over D=128
    #pragma unroll
    for (int n = 0; n < 16; n++)
        #pragma unroll
        for (int v = 0; v < 4; v++) o_[n][v] = 0.0f;
    float m0 = -INFINITY, m1 = -INFINITY, l0 = 0.0f, l1 = 0.0f;

    const int qr = w * 16 + g;

    for (int j = 0; j < S_ / BKV; j++) {
        const int kvBase = j * BKV;

        // ---- Load K and V tiles (tf32) ----
        #pragma unroll
        for (int i = 0; i < 16; i++) {
            int lin = tid + i * 128;
            int r   = lin >> 5;
            int c4  = (lin & 31) << 2;
            const float* kp = &base[(size_t)(kvBase + r) * EQKV + (H_ * D_) + h * D_ + c4];
            float4 kv = *(const float4*)kp;
            float4 ko;
            ko.x = f2tf32(kv.x); ko.y = f2tf32(kv.y);
            ko.z = f2tf32(kv.z); ko.w = f2tf32(kv.w);
            *(float4*)&Ks[r * KPAD + c4] = ko;
            const float* vp = &base[(size_t)(kvBase + r) * EQKV + (2 * H_ * D_) + h * D_ + c4];
            float4 vv = *(const float4*)vp;
            float4 vo;
            vo.x = f2tf32(vv.x); vo.y = f2tf32(vv.y);
            vo.z = f2tf32(vv.z); vo.w = f2tf32(vv.w);
            *(float4*)&Vs[r * VPAD + c4] = vo;
        }
        __syncthreads();

        // ---- S = Q K^T : s-outer (Q frag loaded per k-step), n-inner ----
        float sacc[8][4];
        #pragma unroll
        for (int n = 0; n < 8; n++)
            #pragma unroll
            for (int v = 0; v < 4; v++) sacc[n][v] = 0.0f;
        #pragma unroll
        for (int s = 0; s < 16; s++) {
            const int k0 = s * 8;
            float qa4[4];
            qa4[0] = Qs[qr * QPAD + k0 + t];
            qa4[1] = Qs[(qr + 8) * QPAD + k0 + t];
            qa4[2] = Qs[qr * QPAD + k0 + t + 4];
            qa4[3] = Qs[(qr + 8) * QPAD + k0 + t + 4];
            #pragma unroll
            for (int n = 0; n < 8; n++) {
                float b0 = Ks[(n * 8 + g) * KPAD + k0 + t];
                float b1 = Ks[(n * 8 + g) * KPAD + k0 + t + 4];
                mma_tf32_16x8x8(sacc[n], qa4, b0, b1);
            }
        }

        // ---- Online softmax in registers (rows qr and qr+8) ----
        float mx0 = -INFINITY, mx1 = -INFINITY;
        #pragma unroll
        for (int n = 0; n < 8; n++) {
            mx0 = fmaxf(mx0, fmaxf(sacc[n][0], sacc[n][1]));
            mx1 = fmaxf(mx1, fmaxf(sacc[n][2], sacc[n][3]));
        }
        mx0 = fmaxf(mx0, __shfl_xor_sync(0xFFFFFFFFu, mx0, 1));
        mx0 = fmaxf(mx0, __shfl_xor_sync(0xFFFFFFFFu, mx0, 2));
        mx1 = fmaxf(mx1, __shfl_xor_sync(0xFFFFFFFFu, mx1, 1));
        mx1 = fmaxf(mx1, __shfl_xor_sync(0xFFFFFFFFu, mx1, 2));
        const float mn0 = fmaxf(m0, mx0);
        const float mn1 = fmaxf(m1, mx1);
        const float al0 = __expf(m0 - mn0);
        const float al1 = __expf(m1 - mn1);
        float rs0 = 0.0f, rs1 = 0.0f;
        #pragma unroll
        for (int n = 0; n < 8; n++) {
            float p0 = __expf(sacc[n][0] - mn0);
            float p1 = __expf(sacc[n][1] - mn0);
            float p2 = __expf(sacc[n][2] - mn1);
            float p3 = __expf(sacc[n][3] - mn1);
            rs0 += p0 + p1;  rs1 += p2 + p3;
            sacc[n][0] = f2tf32(p0); sacc[n][1] = f2tf32(p1);
            sacc[n][2] = f2tf32(p2); sacc[n][3] = f2tf32(p3);
        }
        rs0 += __shfl_xor_sync(0xFFFFFFFFu, rs0, 1);
        rs0 += __shfl_xor_sync(0xFFFFFFFFu, rs0, 2);
        rs1 += __shfl_xor_sync(0xFFFFFFFFu, rs1, 1);
        rs1 += __shfl_xor_sync(0xFFFFFFFFu, rs1, 2);
        l0 = l0 * al0 + rs0;  l1 = l1 * al1 + rs1;
        m0 = mn0;             m1 = mn1;

        // ---- Rescale register O by per-row alpha ----
        #pragma unroll
        for (int n = 0; n < 16; n++) {
            o_[n][0] *= al0; o_[n][1] *= al0;
            o_[n][2] *= al1; o_[n][3] *= al1;
        }

        // ---- O += P V : P A-frags built by quad shuffles from sacc ----
        #pragma unroll
        for (int s = 0; s < 8; s++) {
            // A-frag for k-step s: cols s*8+t, s*8+t+4 of P — a permutation
            // of sacc[s] across quad lanes.
            float x0 = __shfl_sync(0xFFFFFFFFu, sacc[s][0], src1);
            float x1 = __shfl_sync(0xFFFFFFFFu, sacc[s][1], src1);
            float x2 = __shfl_sync(0xFFFFFFFFu, sacc[s][2], src1);
            float x3 = __shfl_sync(0xFFFFFFFFu, sacc[s][3], src1);
            float y0 = __shfl_sync(0xFFFFFFFFu, sacc[s][0], src2);
            float y1 = __shfl_sync(0xFFFFFFFFu, sacc[s][1], src2);
            float y2 = __shfl_sync(0xFFFFFFFFu, sacc[s][2], src2);
            float y3 = __shfl_sync(0xFFFFFFFFu, sacc[s][3], src2);
            float pa4[4];
            pa4[0] = odd ? x1 : x0;   // P[qr][s*8+t]
            pa4[1] = odd ? x3 : x2;   // P[qr+8][s*8+t]
            pa4[2] = odd ? y1 : y0;   // P[qr][s*8+t+4]
            pa4[3] = odd ? y3 : y2;   // P[qr+8][s*8+t+4]
            #pragma unroll
            for (int n = 0; n < 16; n++) {
                float b0 = Vs[(s * 8 + t) * VPAD + n * 8 + g];
                float b1 = Vs[(s * 8 + t + 4) * VPAD + n * 8 + g];
                mma_tf32_16x8x8(o_[n], pa4, b0, b1);
            }
        }
        __syncthreads();   // Ks/Vs reads done before next tile's stores
    }

    // ---- Normalize and write out (rows qr, qr+8; cols n*8+2t, +1) ----
    const float inv0 = 1.0f / l0, inv1 = 1.0f / l1;
    const size_t outBase = (size_t)b * S_ * (H_ * D_) + (size_t)h * D_;
    const size_t row0 = (size_t)(qt * BQ + qr) * (H_ * D_);
    const size_t row1 = (size_t)(qt * BQ + qr + 8) * (H_ * D_);
    #pragma unroll
    for (int n = 0; n < 16; n++) {
        int c = n * 8 + 2 * t;
        *(float2*)&out[outBase + row0 + c] = make_float2(o_[n][0] * inv0, o_[n][1] * inv0);
        *(float2*)&out[outBase + row1 + c] = make_float2(o_[n][2] * inv1, o_[n][3] * inv1);
    }
}

// ---------------------------------------------------------------------------
// Launch
// ---------------------------------------------------------------------------
extern "C" void kernel_launch(void* const* d_in, const int* in_sizes, int n_in,
                              void* d_out, int out_size)
{
    const float* x    = (const float*)d_in[0];
    const float* Wqkv = (const float*)d_in[1];
    const float* Wout = (const float*)d_in[2];
    float* out = (float*)d_out;

    float *qkv_ptr = nullptr, *attn_ptr = nullptr;
    cudaGetSymbolAddress((void**)&qkv_ptr, g_qkv);
    cudaGetSymbolAddress((void**)&attn_ptr, g_attn);
    cudaFuncSetAttribute(attn_kernel, cudaFuncAttributeMaxDynamicSharedMemorySize, (int)ATTN_SMEM);

    // 1) QKV projection: [4096,2048] x [6144,2048]^T
    gemm_nt_tf32<<<dim3(EQKV / BN, (B_ * S_) / BM), 256>>>(x, Wqkv, qkv_ptr, B_ * S_, EQKV, DIM_);

    // 2) Attention (raw-mma flash, spill-free)
    attn_kernel<<<dim3(S_ / BQ, H_, B_), 128, ATTN_SMEM>>>(qkv_ptr, attn_ptr);

    // 3) Output projection: [4096,2048] x [2048,2048]^T
    gemm_nt_tf32<<<dim3(DIM_ / BN, (B_ * S_) / BM), 256>>>(attn_ptr, Wout, out, B_ * S_, DIM_, DIM_);
}